// round 9
// baseline (speedup 1.0000x reference)
#include <cuda_runtime.h>
#include <stdint.h>

// Problem constants (fixed by the dataset: B=4, H=376, W=1241, C=64)
#define BATCH   4
#define HH      376
#define WW      1241
#define CC      64
#define HW      (HH * WW)          // 466616  (divisible by 4)
#define NUM_PIX (BATCH * HW)       // 1866464
#define NCOLS   ((NUM_PIX + 127) / 128)   // 14582 columns of 128 pixels

// Scratch: packed (depth_bits<<32 | point_index) per pixel. ~14.9 MB.
__device__ unsigned long long g_keys[NUM_PIX];

// ---------------------------------------------------------------------------
// Projection matrix P = K @ R @ V2P computed inline (identical instruction
// sequence in every thread -> bitwise-identical P everywhere).
// R = [[0,-1,0],[0,0,-1],[1,0,0]]: (K@R)[i] = ( K[i][2], -K[i][0], -K[i][1] )
// ---------------------------------------------------------------------------
__device__ __forceinline__ void compute_P(const float* __restrict__ K, float* P) {
    const float vv = 0.75f;
    const float xo = 0.375f;     // 0.75/2 + 0
    const float yo = -24.625f;   // 0.75/2 - 25
    const float zo = -24.625f;   // 0.75/2 - 25
    #pragma unroll
    for (int i = 0; i < 3; i++) {
        float a =  __ldg(K + i*3 + 2);
        float b = -__ldg(K + i*3 + 0);
        float c = -__ldg(K + i*3 + 1);
        P[i*4+0] = a * vv;
        P[i*4+1] = b * vv;
        P[i*4+2] = c * vv;
        P[i*4+3] = a*xo + b*yo + c*zo;
    }
}

// ---------------------------------------------------------------------------
// Kernel 1: per-point projection + 64-bit packed atomicMin z-buffer.
// (depth_bits<<32 | index): positive-float bits are order-preserving, so one
// atomic gives min-depth with min-index tie-break, matching the reference.
// ---------------------------------------------------------------------------
__global__ void k_scatter(const int* __restrict__ coords,
                          const float* __restrict__ K, int N) {
    int i = blockIdx.x * blockDim.x + threadIdx.x;
    if (i >= N) return;

    float P[12];
    compute_P(K, P);

    int4 c = reinterpret_cast<const int4*>(coords)[i];  // (b, z, y, x)
    float x = (float)c.w;
    float y = (float)c.z;
    float z = (float)c.y;

    float p0 = fmaf(P[0], x, fmaf(P[1], y, fmaf(P[2],  z, P[3])));
    float p1 = fmaf(P[4], x, fmaf(P[5], y, fmaf(P[6],  z, P[7])));
    float d  = fmaf(P[8], x, fmaf(P[9], y, fmaf(P[10], z, P[11])));

    if (d > 1e-6f) {
        // IEEE division so floor boundaries match the fp32 reference
        int u = (int)floorf(__fdiv_rn(p0, d));
        int v = (int)floorf(__fdiv_rn(p1, d));
        if (u >= 0 && u < WW && v >= 0 && v < HH) {
            int pix = c.x * HW + v * WW + u;
            unsigned long long key =
                ((unsigned long long)__float_as_uint(d) << 32) | (unsigned int)i;
            atomicMin(&g_keys[pix], key);
        }
    }
}

// ---------------------------------------------------------------------------
// Kernel 2: fused resolve + gather, one block = one 128-pixel column.
// Phase 1: 64 threads read the column's packed keys ONCE (ulonglong2),
//          write inv_depth (coalesced) and compacted int widx into smem.
// Phase 2: 16 warps, warp w = channel quad w. int4 widx from smem
//          (conflict-free LDS.128), 4 scattered LDG.128 feature reads,
//          register transpose, 4 STG.128 streaming stores.
// Output layout: [B*C*HW] features then [B*HW] inv_depth.
// ---------------------------------------------------------------------------
__global__ void __launch_bounds__(512)
k_gather(const float* __restrict__ feats, float* __restrict__ out) {
    __shared__ int s_widx[128];

    int col = blockIdx.x;
    int tid = threadIdx.x;
    int base = col * 128;                 // first pixel of this column

    // ---- Phase 1: resolve keys -> smem widx + inv_depth output ----
    if (tid < 64) {
        int p = base + tid * 2;           // pixel pair
        int w0 = -1, w1 = -1;
        if (p < NUM_PIX) {
            ulonglong2 kk = __ldg(
                reinterpret_cast<const ulonglong2*>(g_keys) + (base >> 1) + tid);
            w0 = (int)(unsigned)kk.x;     // sentinel low word -> -1
            w1 = (int)(unsigned)kk.y;
            float2 inv;
            inv.x = (w0 >= 0)
                ? __fdiv_rn(1.0f, __uint_as_float((unsigned)(kk.x >> 32))) : 0.0f;
            inv.y = (w1 >= 0)
                ? __fdiv_rn(1.0f, __uint_as_float((unsigned)(kk.y >> 32))) : 0.0f;
            __stcs(reinterpret_cast<float2*>(out + (size_t)NUM_PIX * CC) + (p >> 1), inv);
        }
        s_widx[tid * 2]     = w0;
        s_widx[tid * 2 + 1] = w1;
    }
    __syncthreads();

    // ---- Phase 2: feature gather ----
    int cq = tid >> 5;                    // channel quad 0..15 (= warp id)
    int gl = tid & 31;                    // 4-pixel group within column
    int p0 = base + gl * 4;
    if (p0 >= NUM_PIX) return;

    int4 w = reinterpret_cast<const int4*>(s_widx)[gl];

    const float4 zero = make_float4(0.f, 0.f, 0.f, 0.f);
    float4 f0 = (w.x >= 0)
        ? __ldg(reinterpret_cast<const float4*>(feats + (size_t)w.x * CC) + cq) : zero;
    float4 f1 = (w.y >= 0)
        ? __ldg(reinterpret_cast<const float4*>(feats + (size_t)w.y * CC) + cq) : zero;
    float4 f2 = (w.z >= 0)
        ? __ldg(reinterpret_cast<const float4*>(feats + (size_t)w.z * CC) + cq) : zero;
    float4 f3 = (w.w >= 0)
        ? __ldg(reinterpret_cast<const float4*>(feats + (size_t)w.w * CC) + cq) : zero;

    int b = p0 / HW;                      // group never crosses batch (HW%4==0)
    int r = p0 - b * HW;
    float* op = out + (size_t)(b * CC + 4 * cq) * HW + r;

    float4 o;
    o.x = f0.x; o.y = f1.x; o.z = f2.x; o.w = f3.x;
    __stcs(reinterpret_cast<float4*>(op), o);
    o.x = f0.y; o.y = f1.y; o.z = f2.y; o.w = f3.y;
    __stcs(reinterpret_cast<float4*>(op + (size_t)HW), o);
    o.x = f0.z; o.y = f1.z; o.z = f2.z; o.w = f3.z;
    __stcs(reinterpret_cast<float4*>(op + (size_t)2 * HW), o);
    o.x = f0.w; o.y = f1.w; o.z = f2.w; o.w = f3.w;
    __stcs(reinterpret_cast<float4*>(op + (size_t)3 * HW), o);
}

// ---------------------------------------------------------------------------
extern "C" void kernel_launch(void* const* d_in, const int* in_sizes, int n_in,
                              void* d_out, int out_size) {
    const float* feats  = (const float*)d_in[0];   // (N, 64) f32
    const int*   coords = (const int*)d_in[1];     // (N, 4)  i32
    const float* K      = (const float*)d_in[2];   // (3, 3)  f32

    int N = in_sizes[0] / CC;
    float* out = (float*)d_out;

    // Sentinel fill via memset (0xFF bytes == all-ones keys).
    void* keys_ptr = nullptr;
    cudaGetSymbolAddress(&keys_ptr, g_keys);
    cudaMemsetAsync(keys_ptr, 0xFF, sizeof(unsigned long long) * NUM_PIX);

    const int T = 256;
    k_scatter<<<(N + T - 1) / T, T>>>(coords, K, N);
    k_gather<<<NCOLS, 512>>>(feats, out);
}

// round 11
// speedup vs baseline: 1.0198x; 1.0198x over previous
#include <cuda_runtime.h>
#include <stdint.h>

// Problem constants (fixed by the dataset: B=4, H=376, W=1241, C=64)
#define BATCH   4
#define HH      376
#define WW      1241
#define CC      64
#define HW      (HH * WW)          // 466616  (divisible by 4)
#define NUM_PIX (BATCH * HW)       // 1866464
#define NPIX4   (NUM_PIX / 4)      // 466616
#define NCOL    ((NPIX4 + 31) / 32)   // 14582 columns of 32 pixel-groups

// Scratch: packed (depth_bits<<32 | point_index) per pixel. ~14.9 MB.
__device__ unsigned long long g_keys[NUM_PIX];

// ---------------------------------------------------------------------------
// Projection matrix P = K @ R @ V2P computed inline (identical instruction
// sequence in every thread -> bitwise-identical P everywhere).
// R = [[0,-1,0],[0,0,-1],[1,0,0]]: (K@R)[i] = ( K[i][2], -K[i][0], -K[i][1] )
// ---------------------------------------------------------------------------
__device__ __forceinline__ void compute_P(const float* __restrict__ K, float* P) {
    const float vv = 0.75f;
    const float xo = 0.375f;     // 0.75/2 + 0
    const float yo = -24.625f;   // 0.75/2 - 25
    const float zo = -24.625f;   // 0.75/2 - 25
    #pragma unroll
    for (int i = 0; i < 3; i++) {
        float a =  __ldg(K + i*3 + 2);
        float b = -__ldg(K + i*3 + 0);
        float c = -__ldg(K + i*3 + 1);
        P[i*4+0] = a * vv;
        P[i*4+1] = b * vv;
        P[i*4+2] = c * vv;
        P[i*4+3] = a*xo + b*yo + c*zo;
    }
}

// ---------------------------------------------------------------------------
// Kernel 1: per-point projection + 64-bit packed atomicMin z-buffer.
// (depth_bits<<32 | index): positive-float bits are order-preserving, so one
// atomic gives min-depth with min-index tie-break, matching the reference.
// ---------------------------------------------------------------------------
__global__ void k_scatter(const int* __restrict__ coords,
                          const float* __restrict__ K, int N) {
    int i = blockIdx.x * blockDim.x + threadIdx.x;
    if (i >= N) return;

    float P[12];
    compute_P(K, P);

    int4 c = reinterpret_cast<const int4*>(coords)[i];  // (b, z, y, x)
    float x = (float)c.w;
    float y = (float)c.z;
    float z = (float)c.y;

    float p0 = fmaf(P[0], x, fmaf(P[1], y, fmaf(P[2],  z, P[3])));
    float p1 = fmaf(P[4], x, fmaf(P[5], y, fmaf(P[6],  z, P[7])));
    float d  = fmaf(P[8], x, fmaf(P[9], y, fmaf(P[10], z, P[11])));

    if (d > 1e-6f) {
        // IEEE division so floor boundaries match the fp32 reference
        int u = (int)floorf(__fdiv_rn(p0, d));
        int v = (int)floorf(__fdiv_rn(p1, d));
        if (u >= 0 && u < WW && v >= 0 && v < HH) {
            int pix = c.x * HW + v * WW + u;
            unsigned long long key =
                ((unsigned long long)__float_as_uint(d) << 32) | (unsigned int)i;
            atomicMin(&g_keys[pix], key);
        }
    }
}

// ---------------------------------------------------------------------------
// Kernel 2: fused resolve + gather (barrier-free, R8 structure).
// One thread = TWO channel quads (cq, cq+8) x 4 consecutive pixels:
// 8 independent scattered LDG.128 feature reads and 8 STG.128 streaming
// stores per thread. Key reads per column drop from 16 warps to 8 warps;
// warps remain fully independent (no __syncthreads) so key-load latency
// overlaps across warps. cq==0 warps also emit the inv_depth plane.
// Output layout: [B*C*HW] features then [B*HW] inv_depth.
// ---------------------------------------------------------------------------
__global__ void __launch_bounds__(256)
k_gather(const float* __restrict__ feats, float* __restrict__ out) {
    int i   = blockIdx.x * blockDim.x + threadIdx.x;
    int wid = i >> 5;
    int gl  = i & 31;
    int cq  = wid & 7;           // first channel quad 0..7 (second = cq+8)
    int col = wid >> 3;          // column of 32 pixel-groups
    int pg  = col * 32 + gl;     // global 4-pixel group
    if (pg >= NPIX4) return;

    const ulonglong2* kp = reinterpret_cast<const ulonglong2*>(g_keys) + 2 * pg;
    ulonglong2 ka = __ldg(kp);
    ulonglong2 kb = __ldg(kp + 1);
    // sentinel low word = 0xFFFFFFFF -> -1; winners are small non-negative.
    int w[4] = { (int)(unsigned)ka.x, (int)(unsigned)ka.y,
                 (int)(unsigned)kb.x, (int)(unsigned)kb.y };

    int p0 = pg * 4;
    int b  = p0 / HW;            // group never crosses batch (HW % 4 == 0)
    int r  = p0 - b * HW;

    if (cq == 0) {
        float4 inv;
        unsigned hi[4] = { (unsigned)(ka.x >> 32), (unsigned)(ka.y >> 32),
                           (unsigned)(kb.x >> 32), (unsigned)(kb.y >> 32) };
        #pragma unroll
        for (int j = 0; j < 4; j++) {
            (&inv.x)[j] = (w[j] >= 0)
                ? __fdiv_rn(1.0f, __uint_as_float(hi[j])) : 0.0f;
        }
        __stcs(reinterpret_cast<float4*>(out + (size_t)NUM_PIX * CC) + pg, inv);
    }

    const float4 zero = make_float4(0.f, 0.f, 0.f, 0.f);
    const float4* frow0 = reinterpret_cast<const float4*>(feats + (size_t)w[0] * CC);
    const float4* frow1 = reinterpret_cast<const float4*>(feats + (size_t)w[1] * CC);
    const float4* frow2 = reinterpret_cast<const float4*>(feats + (size_t)w[2] * CC);
    const float4* frow3 = reinterpret_cast<const float4*>(feats + (size_t)w[3] * CC);

    // Both quads' loads issued up front -> 8 outstanding scattered LDG.128.
    float4 fa0 = (w[0] >= 0) ? __ldg(frow0 + cq)     : zero;
    float4 fa1 = (w[1] >= 0) ? __ldg(frow1 + cq)     : zero;
    float4 fa2 = (w[2] >= 0) ? __ldg(frow2 + cq)     : zero;
    float4 fa3 = (w[3] >= 0) ? __ldg(frow3 + cq)     : zero;
    float4 fb0 = (w[0] >= 0) ? __ldg(frow0 + cq + 8) : zero;
    float4 fb1 = (w[1] >= 0) ? __ldg(frow1 + cq + 8) : zero;
    float4 fb2 = (w[2] >= 0) ? __ldg(frow2 + cq + 8) : zero;
    float4 fb3 = (w[3] >= 0) ? __ldg(frow3 + cq + 8) : zero;

    float* opa = out + (size_t)(b * CC + 4 * cq) * HW + r;
    float* opb = opa + (size_t)32 * HW;   // quad cq+8 = +32 channels

    float4 o;
    #pragma unroll
    for (int k = 0; k < 4; k++) {
        o.x = (&fa0.x)[k]; o.y = (&fa1.x)[k]; o.z = (&fa2.x)[k]; o.w = (&fa3.x)[k];
        __stcs(reinterpret_cast<float4*>(opa + (size_t)k * HW), o);
    }
    #pragma unroll
    for (int k = 0; k < 4; k++) {
        o.x = (&fb0.x)[k]; o.y = (&fb1.x)[k]; o.z = (&fb2.x)[k]; o.w = (&fb3.x)[k];
        __stcs(reinterpret_cast<float4*>(opb + (size_t)k * HW), o);
    }
}

// ---------------------------------------------------------------------------
extern "C" void kernel_launch(void* const* d_in, const int* in_sizes, int n_in,
                              void* d_out, int out_size) {
    const float* feats  = (const float*)d_in[0];   // (N, 64) f32
    const int*   coords = (const int*)d_in[1];     // (N, 4)  i32
    const float* K      = (const float*)d_in[2];   // (3, 3)  f32

    int N = in_sizes[0] / CC;
    float* out = (float*)d_out;

    // Sentinel fill via memset (0xFF bytes == all-ones keys).
    void* keys_ptr = nullptr;
    cudaGetSymbolAddress(&keys_ptr, g_keys);
    cudaMemsetAsync(keys_ptr, 0xFF, sizeof(unsigned long long) * NUM_PIX);

    const int T = 256;
    k_scatter<<<(N + T - 1) / T, T>>>(coords, K, N);

    // 8 dual-quad warps per 32-group column; 8 warps per block.
    k_gather<<<NCOL, T>>>(feats, out);
}